// round 14
// baseline (speedup 1.0000x reference)
#include <cuda_runtime.h>
#include <cuda_bf16.h>
#include <math.h>
#include <stdint.h>

// ---------------------------------------------------------------------------
// ChildSumTreeLSTM via HMMA (mma.sync bf16), fp32 accuracy via 3-term split:
//   acc = Ah*Bh + Al*Bh + Ah*Bl   (packed [hi|lo] K=512 rows, 3 passes/chunk)
// iou for internal nodes fused into the per-level GEMM:
//   iou = [hsum | x] @ [Wiouh | Wioux]  (two packed-512 sources, K_eff=1024)
// via g_hsx[internal_node][1024] = [Hh|Hl|Xh|Xl]. The old gemm_big shrinks to
// an f-gate-only GEMM (N=256) run through gemm_dual. Leaf GEMM: 3-stage.
// ---------------------------------------------------------------------------

#define N_NODES   87381
#define N_INT     21845
#define LEAF_OFF  21845
#define N_LEAVES  65536
#define KP        512          // packed row: [hi(256) | lo(256)]
#define L7OFF     5461         // offset of level-7 nodes (= (4^7-1)/3)

#define LSTG      35840        // Ah 10240 | Al 10240 | Bh 7680 | Bl 7680
#define LPITCH    100
#define LEAF_SMEM (3 * LSTG)   // 107520; x2 CTA = 210KB <= 227KB

#define GSTG      40960        // Ah 10240 | Al 10240 | Bh 10240 | Bl 10240
#define BIG_SMEM  (2 * GSTG)   // 81920

// --------------------------- device scratch --------------------------------
__device__ __align__(256) float         g_FX [(size_t)N_INT * 256];      // f-gate x-part
__device__ __align__(256) float         g_c  [(size_t)N_NODES * 256];
__device__ __align__(256) __nv_bfloat16 g_h  [(size_t)N_NODES * KP];
__device__ __align__(256) __nv_bfloat16 g_x  [(size_t)N_NODES * KP];
__device__ __align__(256) __nv_bfloat16 g_hsx[(size_t)N_INT * 1024];     // [Hh|Hl|Xh|Xl]
__device__ __align__(256) float         g_iouh[(size_t)16384 * 768];     // 3j+g
__device__ __align__(256) float         g_fh  [(size_t)65536 * 256];
__device__ __align__(256) __nv_bfloat16 g_Wiou  [ 768 * KP];             // 3j+g (leaf)
__device__ __align__(256) __nv_bfloat16 g_Wiouh2[ 768 * 1024];           // [Wh_h|Wh_l|Wx_h|Wx_l]
__device__ __align__(256) __nv_bfloat16 g_Wfh  [ 256 * KP];
__device__ __align__(256) __nv_bfloat16 g_Wfx  [ 256 * KP];
__device__ float g_b3[768];                                              // 3j+g (bix+bih)
__device__ float g_bf[256];                                              // bfx+bfh

// --------------------------- helpers ---------------------------------------
__device__ __forceinline__ float fsig(float v) {
    return __fdividef(1.0f, 1.0f + __expf(-v));
}
__device__ __forceinline__ float ftanh(float v) {
    float a = fabsf(v);
    float e = __expf(-2.0f * a);
    float t = __fdividef(1.0f - e, 1.0f + e);
    return copysignf(t, v);
}
__device__ __forceinline__ void write2(__nv_bfloat16* row, int j, float v) {
    __nv_bfloat16 hi = __float2bfloat16(v);
    __nv_bfloat16 lo = __float2bfloat16(v - __bfloat162float(hi));
    row[j] = hi; row[256 + j] = lo;
}
__device__ __forceinline__ uint32_t smem_u32(const void* p) {
    uint32_t a;
    asm("{ .reg .u64 t; cvta.to.shared.u64 t, %1; cvt.u32.u64 %0, t; }" : "=r"(a) : "l"(p));
    return a;
}
__device__ __forceinline__ void cp_async16(uint32_t dst, const void* src, int sz) {
    asm volatile("cp.async.ca.shared.global [%0], [%1], 16, %2;"
                 :: "r"(dst), "l"(src), "r"(sz) : "memory");
}
__device__ __forceinline__ void ldmatrix_x4(uint32_t* r, uint32_t addr) {
    asm volatile("ldmatrix.sync.aligned.m8n8.x4.shared.b16 {%0,%1,%2,%3}, [%4];"
                 : "=r"(r[0]), "=r"(r[1]), "=r"(r[2]), "=r"(r[3]) : "r"(addr));
}
__device__ __forceinline__ void mma16816(float* c, const uint32_t* a, const uint32_t* b) {
    asm volatile(
        "mma.sync.aligned.m16n8k16.row.col.f32.bf16.bf16.f32 "
        "{%0,%1,%2,%3}, {%4,%5,%6,%7}, {%8,%9}, {%0,%1,%2,%3};"
        : "+f"(c[0]), "+f"(c[1]), "+f"(c[2]), "+f"(c[3])
        : "r"(a[0]), "r"(a[1]), "r"(a[2]), "r"(a[3]), "r"(b[0]), "r"(b[1]));
}

// --------------------------- pack kernels ----------------------------------
__global__ void split_x(const float* __restrict__ x) {
    const size_t node = blockIdx.x;
    const int j = threadIdx.x;
    const float v = x[node * 256 + j];
    write2(&g_x[node * KP], j, v);
    if (node < N_INT)
        write2(&g_hsx[node * 1024 + 512], j, v);   // Xh at 512+j, Xl at 768+j
}

// Merged weight packs: Wiou(768) | Wiouh2(768) | Wfh(256) | Wfx(256) = 2048 blocks
__global__ void pack_w(const float* __restrict__ Wix, const float* __restrict__ bix,
                       const float* __restrict__ bih,
                       const float* __restrict__ Wiouh, const float* __restrict__ Wfh,
                       const float* __restrict__ Wfx, const float* __restrict__ bfx,
                       const float* __restrict__ bfh) {
    const int b = blockIdx.x;
    const int jj = threadIdx.x;
    if (b < 768) {                      // Wiou row p = 3j+g (leaf)
        const int j = b / 3, g = b % 3;
        write2(&g_Wiou[(size_t)b * KP], jj, Wix[(g * 256 + j) * 256 + jj]);
        if (jj == 0) g_b3[b] = bix[g * 256 + j] + bih[g * 256 + j];
    } else if (b < 1536) {              // Wiouh2 row p = 3j+g: [Wh|Wx] both packed
        const int p = b - 768;
        const int j = p / 3, g = p % 3;
        write2(&g_Wiouh2[(size_t)p * 1024],       jj, Wiouh[(g * 256 + j) * 256 + jj]);
        write2(&g_Wiouh2[(size_t)p * 1024 + 512], jj, Wix  [(g * 256 + j) * 256 + jj]);
    } else if (b < 1792) {              // Wfh row r
        const int r = b - 1536;
        write2(&g_Wfh[(size_t)r * KP], jj, Wfh[r * 256 + jj]);
    } else {                            // Wfx row r
        const int r = b - 1792;
        write2(&g_Wfx[(size_t)r * KP], jj, Wfx[r * 256 + jj]);
        if (jj == 0) g_bf[r] = bfx[r] + bfh[r];
    }
}

// --------------------------- leaf GEMM (128x96, 3-stage, occ2) -------------
// Per k0: load Ah/Al/Bh/Bl tiles once; 3 compute passes (AhBh, AlBh, AhBl).
// Fused activation + level-7 hsum written into g_hsx.
__global__ __launch_bounds__(256, 2)
void gemm_leaf(const __nv_bfloat16* __restrict__ A,      // g_x + LEAF_OFF*KP
               const __nv_bfloat16* __restrict__ B) {    // g_Wiou
    extern __shared__ __align__(16) char smd[];
    const int tid  = threadIdx.x;
    const int wid  = tid >> 5;
    const int lane = tid & 31;
    const int bm = blockIdx.y * 128;
    const int bn = blockIdx.x * 96;
    const int wm = (wid >> 1) * 32;
    const int wn = (wid & 1) * 48;
    const uint32_t sb = smem_u32(smd);

    float acc[2][6][4];
#pragma unroll
    for (int i = 0; i < 2; i++)
#pragma unroll
        for (int n = 0; n < 6; n++)
#pragma unroll
            for (int q = 0; q < 4; q++) acc[i][n][q] = 0.0f;

#define LLOAD(c, st) do {                                                        \
        const int k0e = (c) * 32;                                                \
        uint32_t bs = sb + (st) * LSTG;                                          \
        _Pragma("unroll")                                                        \
        for (int s = 0; s < 7; s++) {                                            \
            int id = tid + s * 256;                                              \
            if (id < 512) {                                                      \
                int r = id >> 2, q = id & 3;                                     \
                cp_async16(bs + r * 80 + q * 16,                                 \
                           A + (size_t)(bm + r) * KP + k0e + q * 8, 16);         \
            } else if (id < 1024) {                                              \
                int o = id - 512; int r = o >> 2, q = o & 3;                     \
                cp_async16(bs + 10240 + r * 80 + q * 16,                         \
                           A + (size_t)(bm + r) * KP + 256 + k0e + q * 8, 16);   \
            } else if (id < 1408) {                                              \
                int o = id - 1024; int r = o >> 2, q = o & 3;                    \
                cp_async16(bs + 20480 + r * 80 + q * 16,                         \
                           B + (size_t)(bn + r) * KP + k0e + q * 8, 16);         \
            } else {                                                             \
                int o = id - 1408; int r = o >> 2, q = o & 3;                    \
                cp_async16(bs + 28160 + r * 80 + q * 16,                         \
                           B + (size_t)(bn + r) * KP + 256 + k0e + q * 8, 16);   \
            }                                                                    \
        }                                                                        \
        asm volatile("cp.async.commit_group;" ::: "memory");                     \
    } while (0)

    LLOAD(0, 0);
    LLOAD(1, 1);
    const uint32_t lrow = lane & 15;
    const uint32_t lcol = (lane >> 4) * 16;

    for (int k0 = 0; k0 < 8; k0++) {
        const int st = k0 % 3;
        if (k0 + 2 < 8) {
            LLOAD(k0 + 2, (k0 + 2) % 3);
            asm volatile("cp.async.wait_group 2;" ::: "memory");
        } else if (k0 + 1 < 8) {
            asm volatile("cp.async.wait_group 1;" ::: "memory");
        } else {
            asm volatile("cp.async.wait_group 0;" ::: "memory");
        }
        __syncthreads();

#pragma unroll 1
        for (int pass = 0; pass < 3; pass++) {
            const uint32_t aoff = (pass == 1) ? 10240u : 0u;
            const uint32_t boff = 20480u + ((pass == 2) ? 7680u : 0u);
            const uint32_t abase = sb + st * LSTG + aoff + (wm + lrow) * 80 + lcol;
            const uint32_t bbase = sb + st * LSTG + boff + (wn + lrow) * 80 + lcol;
#pragma unroll
            for (int ks = 0; ks < 2; ks++) {
                const uint32_t ko = ks * 32;
                uint32_t a[2][4];
                ldmatrix_x4(a[0], abase + ko);
                ldmatrix_x4(a[1], abase + 16 * 80 + ko);
                uint32_t bf[6][2];
#pragma unroll
                for (int j = 0; j < 3; j++) {
                    uint32_t r[4];
                    ldmatrix_x4(r, bbase + j * 16 * 80 + ko);
                    bf[2 * j][0] = r[0]; bf[2 * j][1] = r[2];
                    bf[2 * j + 1][0] = r[1]; bf[2 * j + 1][1] = r[3];
                }
#pragma unroll
                for (int i = 0; i < 2; i++)
#pragma unroll
                    for (int n = 0; n < 6; n++)
                        mma16816(acc[i][n], a[i], bf[n]);
            }
        }
        __syncthreads();
    }
#undef LLOAD

    // ---- stage tile to smem (aliases pipeline buffers) ----
    float* Cs = (float*)smd;
#pragma unroll
    for (int i = 0; i < 2; i++) {
        const int r = wm + i * 16 + (lane >> 2);
#pragma unroll
        for (int n = 0; n < 6; n++) {
            const int col = wn + n * 8 + (lane & 3) * 2;
            *(float2*)(Cs + r * LPITCH + col) = make_float2(acc[i][n][0], acc[i][n][1]);
            *(float2*)(Cs + (r + 8) * LPITCH + col) = make_float2(acc[i][n][2], acc[i][n][3]);
        }
    }
    __syncthreads();

    // ---- leaf activation: 128 rows x 32 features, 2 features per thread ----
    const int j0 = 32 * blockIdx.x;
#pragma unroll 2
    for (int it = 0; it < 8; it++) {
        const int idx = it * 256 + tid;
        const int r = idx >> 4;
        const int t = 2 * (idx & 15);
        float* cr = Cs + r * LPITCH + 3 * t;
        const float* bb = g_b3 + bn + 3 * t;
        float i0 = fsig (cr[0] + bb[0]);
        float o0 = fsig (cr[1] + bb[1]);
        float u0 = ftanh(cr[2] + bb[2]);
        float c0 = i0 * u0;
        float h0 = o0 * ftanh(c0);
        float i1 = fsig (cr[3] + bb[3]);
        float o1 = fsig (cr[4] + bb[4]);
        float u1 = ftanh(cr[5] + bb[5]);
        float c1 = i1 * u1;
        float h1 = o1 * ftanh(c1);

        const size_t node = (size_t)LEAF_OFF + bm + r;
        const int j = j0 + t;
        *(float2*)(g_c + node * 256 + j) = make_float2(c0, c1);

        __nv_bfloat16 hh0 = __float2bfloat16(h0);
        __nv_bfloat16 hh1 = __float2bfloat16(h1);
        float l0 = h0 - __bfloat162float(hh0);
        float l1 = h1 - __bfloat162float(hh1);
        uint32_t hiw; { __nv_bfloat162 p2 = {hh0, hh1}; hiw = *reinterpret_cast<uint32_t*>(&p2); }
        uint32_t low; { __nv_bfloat162 p2 = __floats2bfloat162_rn(l0, l1);
                        low = *reinterpret_cast<uint32_t*>(&p2); }
        uint32_t* hrow = (uint32_t*)(g_h + node * KP + j);
        hrow[0] = hiw;
        hrow[128] = low;

        // in-place fp32 h staging for the fused hsum pass
        cr[0] = h0;
        cr[3] = h1;
    }
    __syncthreads();

    // ---- fused level-7 hsum -> g_hsx rows L7OFF + parent ----
    const int kb = 32 * blockIdx.y;
#pragma unroll
    for (int v = 0; v < 4; v++) {
        const int lin = v * 256 + tid;
        const int pp = lin >> 5;
        const int tt = lin & 31;
        const float* hb = Cs + (4 * pp) * LPITCH + 3 * tt;
        float s = hb[0] + hb[LPITCH] + hb[2 * LPITCH] + hb[3 * LPITCH];
        write2(&g_hsx[(size_t)(L7OFF + kb + pp) * 1024], j0 + tt, s);
    }
}

// --------------------------- generic 128x128 mainloop ----------------------
// nsA sources: row stride = nsA*512; chunks = nsA*8; chunk c -> src c>>3.
__device__ __forceinline__ void mainloop128(
    const __nv_bfloat16* __restrict__ A, const __nv_bfloat16* __restrict__ B,
    int M, int bm, int bn, int nsA, uint32_t sb, int tid, int wid, int lane,
    float (&acc)[2][8][4])
{
    const int wm = (wid >> 1) * 32;
    const int wn = (wid & 1) * 64;
    const int rowA = nsA * 512;
    const int ncht = nsA * 8;

#define GLOAD(c, st) do {                                                        \
        const int colh = ((c) >> 3) * 512 + ((c) & 7) * 32;                      \
        uint32_t bs = sb + (st) * GSTG;                                          \
        _Pragma("unroll")                                                        \
        for (int s = 0; s < 8; s++) {                                            \
            int id = tid + s * 256;                                              \
            int seg = id >> 9;                                                   \
            int o = id & 511;                                                    \
            int r = o >> 2, q = o & 3;                                           \
            if (seg == 0)                                                        \
                cp_async16(bs + r * 80 + q * 16,                                 \
                           A + (size_t)(bm + r) * rowA + colh + q * 8,           \
                           (bm + r < M) ? 16 : 0);                               \
            else if (seg == 1)                                                   \
                cp_async16(bs + 10240 + r * 80 + q * 16,                         \
                           A + (size_t)(bm + r) * rowA + colh + 256 + q * 8,     \
                           (bm + r < M) ? 16 : 0);                               \
            else if (seg == 2)                                                   \
                cp_async16(bs + 20480 + r * 80 + q * 16,                         \
                           B + (size_t)(bn + r) * rowA + colh + q * 8, 16);      \
            else                                                                 \
                cp_async16(bs + 30720 + r * 80 + q * 16,                         \
                           B + (size_t)(bn + r) * rowA + colh + 256 + q * 8, 16);\
        }                                                                        \
        asm volatile("cp.async.commit_group;" ::: "memory");                     \
    } while (0)

    GLOAD(0, 0);
    const uint32_t lrow = lane & 15;
    const uint32_t lcol = (lane >> 4) * 16;

    for (int c = 0; c < ncht; c++) {
        const int st = c & 1;
        if (c + 1 < ncht) {
            GLOAD(c + 1, st ^ 1);
            asm volatile("cp.async.wait_group 1;" ::: "memory");
        } else {
            asm volatile("cp.async.wait_group 0;" ::: "memory");
        }
        __syncthreads();

#pragma unroll 1
        for (int pass = 0; pass < 3; pass++) {
            const uint32_t aoff = (pass == 1) ? 10240u : 0u;
            const uint32_t boff = 20480u + ((pass == 2) ? 10240u : 0u);
            const uint32_t abase = sb + st * GSTG + aoff + (wm + lrow) * 80 + lcol;
            const uint32_t bbase = sb + st * GSTG + boff + (wn + lrow) * 80 + lcol;
#pragma unroll
            for (int ks = 0; ks < 2; ks++) {
                const uint32_t ko = ks * 32;
                uint32_t a[2][4];
                ldmatrix_x4(a[0], abase + ko);
                ldmatrix_x4(a[1], abase + 16 * 80 + ko);
                uint32_t bf[8][2];
#pragma unroll
                for (int j = 0; j < 4; j++) {
                    uint32_t r[4];
                    ldmatrix_x4(r, bbase + j * 16 * 80 + ko);
                    bf[2 * j][0] = r[0]; bf[2 * j][1] = r[2];
                    bf[2 * j + 1][0] = r[1]; bf[2 * j + 1][1] = r[3];
                }
#pragma unroll
                for (int i = 0; i < 2; i++)
#pragma unroll
                    for (int n = 0; n < 8; n++)
                        mma16816(acc[i][n], a[i], bf[n]);
            }
        }
        __syncthreads();
    }
#undef GLOAD
}

// --------------------------- dual-problem GEMM -----------------------------
__global__ __launch_bounds__(256, 2)
void gemm_dual(const __nv_bfloat16* A1, const __nv_bfloat16* B1, float* C1,
               int M1, int N1, int ns1,
               const __nv_bfloat16* A2, const __nv_bfloat16* B2, float* C2,
               int M2, int N2, int ns2) {
    extern __shared__ __align__(16) char smd[];
    const int tid  = threadIdx.x;
    const int wid  = tid >> 5;
    const int lane = tid & 31;
    const uint32_t sb = smem_u32(smd);

    const __nv_bfloat16 *A, *B;
    float* C;
    int M, Ntot, bm, bn, ns;
    {
        const int nt1 = N1 >> 7, mt1 = (M1 + 127) >> 7;
        const int t1 = nt1 * mt1;
        int idx = blockIdx.x;
        if (idx < t1) {
            A = A1; B = B1; C = C1; M = M1; Ntot = N1; ns = ns1;
            bm = (idx / nt1) * 128; bn = (idx % nt1) * 128;
        } else {
            idx -= t1;
            const int nt2 = N2 >> 7;
            A = A2; B = B2; C = C2; M = M2; Ntot = N2; ns = ns2;
            bm = (idx / nt2) * 128; bn = (idx % nt2) * 128;
        }
    }

    float acc[2][8][4];
#pragma unroll
    for (int i = 0; i < 2; i++)
#pragma unroll
        for (int n = 0; n < 8; n++)
#pragma unroll
            for (int q = 0; q < 4; q++) acc[i][n][q] = 0.0f;

    mainloop128(A, B, M, bm, bn, ns, sb, tid, wid, lane, acc);

    const int wm = (wid >> 1) * 32;
    const int wn = (wid & 1) * 64;
#pragma unroll
    for (int i = 0; i < 2; i++) {
        const int ra = bm + wm + i * 16 + (lane >> 2);
        const int rb = ra + 8;
#pragma unroll
        for (int n = 0; n < 8; n++) {
            const int col = bn + wn + n * 8 + (lane & 3) * 2;
            if (ra < M)
                *(float2*)(C + (size_t)ra * Ntot + col) =
                    make_float2(acc[i][n][0], acc[i][n][1]);
            if (rb < M)
                *(float2*)(C + (size_t)rb * Ntot + col) =
                    make_float2(acc[i][n][2], acc[i][n][3]);
        }
    }
}

// --------------------------- fused combine + parent hsum -------------------
__global__ void combine_fused(int node_off, int child_off, int parent_off) {
    __shared__ float hsm[4][256];
    const int s = threadIdx.x >> 8;
    const int j = threadIdx.x & 255;
    const int k = 4 * blockIdx.x + s;
    const size_t node = (size_t)node_off + k;

    const float* iouh = &g_iouh[(size_t)k * 768 + 3 * j];
    const float* b3 = &g_b3[3 * j];

    float iv = fsig (iouh[0] + b3[0]);
    float ov = fsig (iouh[1] + b3[1]);
    float uv = ftanh(iouh[2] + b3[2]);
    const float fx = g_FX[node * 256 + j] + g_bf[j];

    float acc = 0.0f;
#pragma unroll
    for (int b = 0; b < 4; b++) {
        size_t ch = (size_t)child_off + 4 * (size_t)k + b;
        float f = fsig(fx + g_fh[(4 * (size_t)k + b) * 256 + j]);
        acc = fmaf(f, g_c[ch * 256 + j], acc);
    }
    float c = fmaf(iv, uv, acc);
    float h = ov * ftanh(c);
    g_c[node * 256 + j] = c;
    write2(&g_h[node * KP], j, h);

    hsm[s][j] = h;
    __syncthreads();
    if (s == 0) {
        float sum = hsm[0][j] + hsm[1][j] + hsm[2][j] + hsm[3][j];
        write2(&g_hsx[(size_t)(parent_off + blockIdx.x) * 1024], j, sum);
    }
}

__global__ void combine_root() {
    const int j = threadIdx.x;
    const float* iouh = &g_iouh[3 * j];
    float iv = fsig (iouh[0] + g_b3[3 * j]);
    float ov = fsig (iouh[1] + g_b3[3 * j + 1]);
    float uv = ftanh(iouh[2] + g_b3[3 * j + 2]);
    const float fx = g_FX[j] + g_bf[j];
    float acc = 0.0f;
#pragma unroll
    for (int b = 0; b < 4; b++) {
        float f = fsig(fx + g_fh[b * 256 + j]);
        acc = fmaf(f, g_c[(1 + b) * 256 + j], acc);
    }
    float c = fmaf(iv, uv, acc);
    float h = ov * ftanh(c);
    g_c[j] = c;
    write2(&g_h[0], j, h);
}

__global__ void write_out(float* __restrict__ out) {
    int j = threadIdx.x;
    if (blockIdx.x == 0) out[j] = g_c[j];
    else out[256 + j] = __bfloat162float(g_h[j]) + __bfloat162float(g_h[256 + j]);
}

// --------------------------- launcher --------------------------------------
extern "C" void kernel_launch(void* const* d_in, const int* in_sizes, int n_in,
                              void* d_out, int out_size) {
    const float* x      = (const float*)d_in[0];
    const float* W_ioux = (const float*)d_in[1];
    const float* b_ioux = (const float*)d_in[2];
    const float* W_iouh = (const float*)d_in[3];
    const float* b_iouh = (const float*)d_in[4];
    const float* W_fx   = (const float*)d_in[5];
    const float* b_fx   = (const float*)d_in[6];
    const float* W_fh   = (const float*)d_in[7];
    const float* b_fh   = (const float*)d_in[8];

    cudaFuncSetAttribute(gemm_dual, cudaFuncAttributeMaxDynamicSharedMemorySize, BIG_SMEM);
    cudaFuncSetAttribute(gemm_leaf, cudaFuncAttributeMaxDynamicSharedMemorySize, LEAF_SMEM);

    __nv_bfloat16 *xp, *hp, *hsxp, *wlp, *wi2p, *wfhp, *wfxp;
    float *iouh, *fh, *fxp;
    cudaGetSymbolAddress((void**)&xp,   g_x);
    cudaGetSymbolAddress((void**)&hp,   g_h);
    cudaGetSymbolAddress((void**)&hsxp, g_hsx);
    cudaGetSymbolAddress((void**)&wlp,  g_Wiou);
    cudaGetSymbolAddress((void**)&wi2p, g_Wiouh2);
    cudaGetSymbolAddress((void**)&wfhp, g_Wfh);
    cudaGetSymbolAddress((void**)&wfxp, g_Wfx);
    cudaGetSymbolAddress((void**)&iouh, g_iouh);
    cudaGetSymbolAddress((void**)&fh,   g_fh);
    cudaGetSymbolAddress((void**)&fxp,  g_FX);

    // 1-2: pack / split
    split_x<<<N_NODES, 256>>>(x);
    pack_w<<<2048, 256>>>(W_ioux, b_ioux, b_iouh, W_iouh, W_fh, W_fx, b_fx, b_fh);

    // 3: f-gate x-GEMM (single problem through gemm_dual): FX = x_int @ Wfx^T
    {
        int tiles = ((N_INT + 127) / 128) * 2;   // N=256 -> 2 col tiles
        gemm_dual<<<tiles, 256, BIG_SMEM>>>(xp, wfxp, fxp, N_INT, 256, 1,
                                            xp, wfxp, fxp, 0, 128, 1);
    }

    // 4: leaf GEMM + fused activation + fused level-7 hsum (PROFILED LAUNCH)
    {
        dim3 grid(8, N_LEAVES / 128);
        gemm_leaf<<<grid, 256, LEAF_SMEM>>>(&xp[(size_t)LEAF_OFF * KP], wlp);
    }

    // internal levels l = 7..0
    for (int l = 7; l >= 0; l--) {
        int n = 1 << (2 * l);
        int off = ((1 << (2 * l)) - 1) / 3;
        int choff = off + n;

        {   // fused dual GEMM: IOU' = [hsum|x] @ [Wh|Wx]  (n x 768, 2 sources)
            //                + FH = h_children @ Wfh^T    (4n x 256, 1 source)
            int mt1 = (n + 127) / 128;
            int mt2 = (4 * n + 127) / 128;
            int tiles = mt1 * 6 + mt2 * 2;
            gemm_dual<<<tiles, 256, BIG_SMEM>>>(
                &hsxp[(size_t)off * 1024], wi2p, iouh, n, 768, 2,
                &hp[(size_t)choff * KP], wfhp, fh, 4 * n, 256, 1);
        }
        if (l > 0) {
            int parent_off = ((1 << (2 * (l - 1))) - 1) / 3;
            combine_fused<<<n / 4, 1024>>>(off, choff, parent_off);
        } else {
            combine_root<<<1, 256>>>();
        }
    }

    write_out<<<2, 256>>>((float*)d_out);
}